// round 12
// baseline (speedup 1.0000x reference)
#include <cuda_runtime.h>
#include <cstdint>

// Problem constants (fixed for this problem instance)
#define RR 20000   // reviews
#define SS 64      // words per review
#define DD 128     // embedding dim
#define KK 32      // aspects
#define BB 2048    // batch
#define LL 20480   // history length (both user and item)
#define PER (LL / BB)   // 10: exact entries per segment (seg = arange(L)//(L/B))

#define GRID_REVIEW 592   // 4 blocks/SM x 148 SMs

// ---------------- device scratch (no allocation allowed) ----------------
__device__ float g_v[RR * DD];    // v[r] = M_w @ y[r]
__device__ float g_rs[RR * DD];   // per-review aspect embedding r_s

// ---- packed fp32x2 helpers (FFMA2: 2x fp32 issue rate on sm_103a) ----
#define FMA2(acc, a, b) \
    asm("fma.rn.f32x2 %0, %1, %2, %0;" : "+l"(acc) : "l"(a), "l"(b))
#define PACK2(dst, xu) \
    asm("mov.b64 %0, {%1, %1};" : "=l"(dst) : "r"(xu))
#define UNPACK2(lo, hi, src) \
    asm("mov.b64 {%0, %1}, %2;" : "=r"(lo), "=r"(hi) : "l"(src))

// ================= kernel 1: v[r,d] = sum_e M_w[d,e] * y[r,e] =================
// Grid-occupancy layout: 625 blocks x 32 reviews -> 4.2 blocks/SM, occ cap 4
// (32 warps/SM). Thread tile = 4 reviews x 4 d (one ull2): per e,
// 1 LDS.128 + 8 FFMA2 (reuse ratio unchanged), acc = 8 ull = 16 regs,
// ~40 regs total. Floors: FFMA2 ~9.6us, LDS ~9.4us.
__global__ void __launch_bounds__(256, 4) vprep_kernel(
    const float* __restrict__ Mw,    // [D,D] row-major: Mw[d*DD+e]
    const float* __restrict__ ypos)  // [R,D]
{
    __shared__ float mw_sh[64 * 132];   // [e_local][d], padded row stride 132

    const int t  = threadIdx.x;
    const int dg = t & 31;       // ull2 chunk: d = 4*dg
    const int rg = t >> 5;       // 0..7 -> 4 reviews each
    int rbase = blockIdx.x * 32 + rg * 4;
    if (rbase > RR - 4) rbase = RR - 4;   // tail clamp: duplicate work, same values
    const float* yb = ypos + (size_t)rbase * DD;

    unsigned long long acc[4][2];   // [review][half of ull2]
    #pragma unroll
    for (int rv = 0; rv < 4; ++rv) { acc[rv][0] = 0ull; acc[rv][1] = 0ull; }

    for (int h = 0; h < 2; ++h) {           // two 64-e halves of M_w
        __syncthreads();
        for (int i = t; i < 128 * 64; i += 256) {
            int el = i >> 7, d = i & 127;                    // consecutive t -> consecutive d
            mw_sh[el * 132 + d] = Mw[d * DD + h * 64 + el];  // strided LDG, coalesced STS
        }
        __syncthreads();

        #pragma unroll 4
        for (int e2 = 0; e2 < 32; ++e2) {
            float2 ya[4];
            #pragma unroll
            for (int rv = 0; rv < 4; ++rv)
                ya[rv] = *reinterpret_cast<const float2*>(
                             yb + rv * DD + h * 64 + e2 * 2);   // broadcast LDG.64

            #pragma unroll
            for (int j2 = 0; j2 < 2; ++j2) {
                const int e = e2 * 2 + j2;
                const ulonglong2 m = reinterpret_cast<const ulonglong2*>(
                                         mw_sh + e * 132)[dg];   // conflict-free LDS.128
                #pragma unroll
                for (int rv = 0; rv < 4; ++rv) {
                    unsigned long long pr;
                    PACK2(pr, __float_as_uint(j2 ? ya[rv].y : ya[rv].x));
                    FMA2(acc[rv][0], m.x, pr);
                    FMA2(acc[rv][1], m.y, pr);
                }
            }
        }
    }

    #pragma unroll
    for (int rv = 0; rv < 4; ++rv) {
        unsigned v0, v1, v2, v3;
        UNPACK2(v0, v1, acc[rv][0]);
        UNPACK2(v2, v3, acc[rv][1]);
        float4 o = make_float4(__uint_as_float(v0), __uint_as_float(v1),
                               __uint_as_float(v2), __uint_as_float(v3));
        *reinterpret_cast<float4*>(g_v + (size_t)(rbase + rv) * DD + 4 * dg) = o;
    }
}

// ================= kernel 2: persistent fused review pipeline =================
// Software pipeline across grid-stride iterations: the NEXT review's 8 wemb
// row gathers are issued right after the current z-partial frees ev[].
// K-softmax runs in warp 0 only -> p_sh; r_s phase reads p via LDS broadcast.
__global__ void __launch_bounds__(256, 4) review_kernel(
    const int*   __restrict__ tok,    // [R,S]
    const float* __restrict__ wemb,   // [V,D]
    const float* __restrict__ Ww,     // [D,K]
    const float* __restrict__ Wb,     // [K]
    const float* __restrict__ Tw,     // [K,D]
    const float* __restrict__ Tb)     // [D]
{
    __shared__ float wwS[KK * 129];   // [k][d], stride 129 -> bank (k+d)%32
    __shared__ float twS[KK * DD];    // [k][d]
    __shared__ float wb_sh[KK];
    __shared__ float v_sh[DD];
    __shared__ float ax_sh[SS];
    __shared__ float red[8 * DD];     // per-warp z partials
    __shared__ float z_sh[DD];
    __shared__ float lpart[8 * KK];
    __shared__ float p_sh[KK];

    const int t    = threadIdx.x;
    const int lane = t & 31;
    const int w    = t >> 5;

    // ---- one-time per-block staging ----
    for (int i = t; i < DD * KK; i += 256) {
        int d = i >> 5, k = i & 31;
        wwS[k * 129 + d] = Ww[i];
        twS[i] = Tw[i];
    }
    if (t < KK) wb_sh[t] = Wb[t];
    const float tb_reg = (t < DD) ? Tb[t] : 0.f;
    const int   part   = t >> 5;
    const float* wwrow = wwS + lane * 129 + part * 16;   // lane = logit k

    // ---- prologue: first review's tokens (per-warp regs), v, and gathers ----
    const int rfirst = blockIdx.x;
    int tokreg = 0;
    if (lane < 8) tokreg = __ldg(tok + rfirst * SS + w * 8 + lane);
    float v_pf = (t < DD) ? g_v[(size_t)rfirst * DD + t] : 0.f;

    float4 ev[8];
    #pragma unroll
    for (int i = 0; i < 8; ++i) {
        int id = __shfl_sync(0xffffffffu, tokreg, i);
        ev[i] = reinterpret_cast<const float4*>(wemb + (size_t)id * DD)[lane];
    }
    if (t < DD) v_sh[t] = v_pf;
    __syncthreads();

    for (int r = rfirst; r < RR; r += GRID_REVIEW) {
        const int rn = r + GRID_REVIEW;
        const int rc = (rn < RR) ? rn : r;

        const float4 v4 = reinterpret_cast<float4*>(v_sh)[lane];

        // ---- per-lane partial dots for this warp's 8 s-values ----
        float p[8];
        #pragma unroll
        for (int i = 0; i < 8; ++i)
            p[i] = ev[i].x * v4.x + ev[i].y * v4.y +
                   ev[i].z * v4.z + ev[i].w * v4.w;

        // ---- prefetch next review's tokens + v (regs; consumed in tail) ----
        int tokreg_n = 0;
        if (lane < 8) tokreg_n = __ldg(tok + rc * SS + w * 8 + lane);
        float v_pf_n = (t < DD) ? g_v[(size_t)rc * DD + t] : 0.f;

        // ---- folding multi-reduce: 8 dots -> 9 shfls ----
        float q[4];
        #pragma unroll
        for (int i = 0; i < 4; ++i) {
            float send = (lane & 16) ? p[i] : p[i + 4];
            float keep = (lane & 16) ? p[i + 4] : p[i];
            q[i] = keep + __shfl_xor_sync(0xffffffffu, send, 16);
        }
        float u[2];
        #pragma unroll
        for (int i = 0; i < 2; ++i) {
            float send = (lane & 8) ? q[i] : q[i + 2];
            float keep = (lane & 8) ? q[i + 2] : q[i];
            u[i] = keep + __shfl_xor_sync(0xffffffffu, send, 8);
        }
        float dx;
        {
            float send = (lane & 4) ? u[0] : u[1];
            float keep = (lane & 4) ? u[1] : u[0];
            dx = keep + __shfl_xor_sync(0xffffffffu, send, 4);
        }
        dx += __shfl_xor_sync(0xffffffffu, dx, 2);
        dx += __shfl_xor_sync(0xffffffffu, dx, 1);
        if ((lane & 3) == 0) ax_sh[w * 8 + ((lane >> 2) & 7)] = dx;
        __syncthreads();                                   // B1

        // ---- softmax over S=64 (redundant in every warp) + z partial ----
        float4 z = make_float4(0.f, 0.f, 0.f, 0.f);
        {
            float a = ax_sh[lane];
            float b = ax_sh[lane + 32];
            float m = fmaxf(a, b);
            #pragma unroll
            for (int o = 16; o; o >>= 1) m = fmaxf(m, __shfl_xor_sync(0xffffffffu, m, o));
            float ea = __expf(a - m), eb = __expf(b - m);
            float s = ea + eb;
            #pragma unroll
            for (int o = 16; o; o >>= 1) s += __shfl_xor_sync(0xffffffffu, s, o);
            float inv = __fdividef(1.f, s);
            float sel  = (w & 4) ? eb : ea;
            int   base = (w & 3) * 8;
            #pragma unroll
            for (int i = 0; i < 8; ++i) {
                float av = __shfl_sync(0xffffffffu, sel, base + i) * inv;
                z.x = fmaf(av, ev[i].x, z.x);
                z.y = fmaf(av, ev[i].y, z.y);
                z.z = fmaf(av, ev[i].z, z.z);
                z.w = fmaf(av, ev[i].w, z.w);
            }
        }

        // ---- ev[] now dead: ISSUE NEXT REVIEW'S GATHERS (latency hides
        //      under the whole aspect tail below) ----
        #pragma unroll
        for (int i = 0; i < 8; ++i) {
            int id = __shfl_sync(0xffffffffu, tokreg_n, i);
            ev[i] = reinterpret_cast<const float4*>(wemb + (size_t)id * DD)[lane];
        }

        reinterpret_cast<float4*>(red)[w * 32 + lane] = z;
        __syncthreads();                                   // B2

        // ---- z[d]: cross-warp sum of 8 partials ----
        if (t < DD) {
            float s = 0.f;
            #pragma unroll
            for (int w2 = 0; w2 < 8; ++w2)
                s += red[w2 * DD + t];
            z_sh[t] = s;
        }
        __syncthreads();                                   // B3

        // ---- aspect logits: thread (part, lane=k) -> 16-d partial ----
        {
            float a = 0.f;
            const float* zp = z_sh + part * 16;
            #pragma unroll
            for (int j = 0; j < 16; ++j)
                a = fmaf(zp[j], wwrow[j], a);
            lpart[part * KK + lane] = a;
        }
        __syncthreads();                                   // B4

        // ---- K-softmax: warp 0 only -> p_sh ----
        if (w == 0) {
            float a = wb_sh[lane];
            #pragma unroll
            for (int pp = 0; pp < 8; ++pp) a += lpart[pp * KK + lane];
            float m = a;
            #pragma unroll
            for (int o = 16; o; o >>= 1) m = fmaxf(m, __shfl_xor_sync(0xffffffffu, m, o));
            float e = __expf(a - m);
            float s = e;
            #pragma unroll
            for (int o = 16; o; o >>= 1) s += __shfl_xor_sync(0xffffffffu, s, o);
            p_sh[lane] = e * __fdividef(1.f, s);
        }
        __syncthreads();                                   // B5

        // ---- r_s[d] = Tb[d] + sum_k p[k] * Tw[k][d] (p via LDS broadcast) ----
        if (t < DD) {
            float a = tb_reg;
            #pragma unroll
            for (int k = 0; k < KK; ++k)
                a = fmaf(p_sh[k], twS[k * DD + t], a);
            g_rs[(size_t)r * DD + t] = a;
        }

        // ---- stage next v into SMEM; rotate token regs ----
        if (t < DD) v_sh[t] = v_pf_n;
        tokreg = tokreg_n;
        __syncthreads();   // B6: protects ax_sh/red/lpart/p_sh/v_sh for next iter
    }
}

// ================= kernel 3: fused segment-mean + prediction =================
__global__ void __launch_bounds__(256) final_kernel(
    const int*   __restrict__ user, const int* __restrict__ item,
    const int*   __restrict__ uidx, const int* __restrict__ iidx,
    const float* __restrict__ uemb, const float* __restrict__ iemb,
    const float* __restrict__ avg,  float* __restrict__ out)
{
    __shared__ float sh[256];
    __shared__ float red[4];

    const int b    = blockIdx.x;
    const int t    = threadIdx.x;
    const int side = t >> 7;          // 0 = user, 1 = item
    const int d    = t & 127;

    float uf = 0.f, itf = 0.f;
    if (t < DD) {
        uf  = uemb[(size_t)user[b] * DD + t];
        itf = iemb[(size_t)item[b] * DD + t];
    }

    const int* idxp = side ? iidx : uidx;
    const int  base = b * PER;

    int ids[PER];
    #pragma unroll
    for (int j = 0; j < PER; ++j)
        ids[j] = __ldg(idxp + base + j);      // PER independent LDG

    float sum = 0.f;
    #pragma unroll
    for (int j = 0; j < PER; ++j)
        sum += g_rs[(size_t)ids[j] * DD + d]; // PER independent LDG

    sh[t] = sum * (1.0f / (float)PER);
    __syncthreads();

    if (t < DD) {
        float p = sh[t] * sh[t + 128] + uf * itf;
        #pragma unroll
        for (int o = 16; o; o >>= 1) p += __shfl_xor_sync(0xffffffffu, p, o);
        if ((t & 31) == 0) red[t >> 5] = p;
    }
    __syncthreads();
    if (t == 0) out[b] = red[0] + red[1] + red[2] + red[3] + avg[0];
}

// ---------------- launch ----------------
extern "C" void kernel_launch(void* const* d_in, const int* in_sizes, int n_in,
                              void* d_out, int out_size)
{
    const int*   user = (const int*)  d_in[0];
    const int*   item = (const int*)  d_in[1];
    const int*   hrev = (const int*)  d_in[2];
    const float* ypos = (const float*)d_in[3];
    const int*   uidx = (const int*)  d_in[4];
    const int*   iidx = (const int*)  d_in[6];
    const float* wemb = (const float*)d_in[8];
    const float* Mw   = (const float*)d_in[9];
    // d_in[10] = M_b: constant shift over s -> cancels in softmax, unused
    const float* Ww   = (const float*)d_in[11];
    const float* Wb   = (const float*)d_in[12];
    const float* Tw   = (const float*)d_in[13];
    const float* Tb   = (const float*)d_in[14];
    const float* uemb = (const float*)d_in[15];
    const float* iemb = (const float*)d_in[16];
    const float* avg  = (const float*)d_in[17];
    float* out = (float*)d_out;

    vprep_kernel <<<(RR + 31) / 32, 256>>>(Mw, ypos);   // 625 blocks x 32 reviews
    review_kernel<<<GRID_REVIEW, 256>>>(hrev, wemb, Ww, Wb, Tw, Tb);
    final_kernel <<<BB, 256>>>(user, item, uidx, iidx, uemb, iemb, avg, out);
}

// round 13
// speedup vs baseline: 1.3554x; 1.3554x over previous
#include <cuda_runtime.h>
#include <cstdint>

// Problem constants (fixed for this problem instance)
#define RR 20000   // reviews
#define SS 64      // words per review
#define DD 128     // embedding dim
#define KK 32      // aspects
#define BB 2048    // batch
#define LL 20480   // history length (both user and item)
#define PER (LL / BB)   // 10: exact entries per segment (seg = arange(L)//(L/B))

#define GRID_REVIEW 592   // 4 blocks/SM x 148 SMs

// ---------------- device scratch (no allocation allowed) ----------------
__device__ float g_v[RR * DD];    // v[r] = M_w @ y[r]
__device__ float g_rs[RR * DD];   // per-review aspect embedding r_s

// ---- packed fp32x2 helpers (FFMA2: 2x fp32 issue rate on sm_103a) ----
#define FMA2(acc, a, b) \
    asm("fma.rn.f32x2 %0, %1, %2, %0;" : "+l"(acc) : "l"(a), "l"(b))
#define PACK2(dst, xu) \
    asm("mov.b64 %0, {%1, %1};" : "=l"(dst) : "r"(xu))
#define UNPACK2(lo, hi, src) \
    asm("mov.b64 {%0, %1}, %2;" : "=r"(lo), "=r"(hi) : "l"(src))

// ================= kernel 1: v[r,d] = sum_e M_w[d,e] * y[r,e] =================
// Single-wave + broadcast-sharing layout: 625 blocks x 32 reviews x 128 thr.
// Thread tile = 4 reviews x 8 d (d = 4*dg + 64*j); warp = 2 review-groups x
// 16 dg -> both half-warps read the SAME mw_sh addresses (HW broadcast):
// each LDS.128 moves 256B of crossbar and feeds 8 reviews (2 MAC/byte).
// 6 blocks/SM (34KB SMEM) -> 888 slots >= 625 -> ONE wave, no tail.
__global__ void __launch_bounds__(128, 6) vprep_kernel(
    const float* __restrict__ Mw,    // [D,D] row-major: Mw[d*DD+e]
    const float* __restrict__ ypos)  // [R,D]
{
    __shared__ float mw_sh[64 * 132];   // [e_local][d], padded row stride 132

    const int t  = threadIdx.x;          // 0..127
    const int dg = t & 15;               // d chunk: d = 4*dg + 64*j
    const int rg = t >> 4;               // 0..7 -> 4 reviews each
    const int rbase = blockIdx.x * 32 + rg * 4;   // 625*32 = 20000 exact
    const float* yb = ypos + (size_t)rbase * DD;

    unsigned long long acc[4][2][2];   // [review][j][half]
    #pragma unroll
    for (int rv = 0; rv < 4; ++rv)
        #pragma unroll
        for (int j = 0; j < 2; ++j) { acc[rv][j][0] = 0ull; acc[rv][j][1] = 0ull; }

    for (int h = 0; h < 2; ++h) {           // two 64-e halves of M_w
        __syncthreads();
        for (int i = t; i < 128 * 64; i += 128) {
            int d = i >> 6, el = i & 63;                     // coalesced LDG
            mw_sh[el * 132 + d] = Mw[d * DD + h * 64 + el];
        }
        __syncthreads();

        #pragma unroll 4
        for (int e2 = 0; e2 < 32; ++e2) {
            float2 ya[4];
            #pragma unroll
            for (int rv = 0; rv < 4; ++rv)
                ya[rv] = *reinterpret_cast<const float2*>(
                             yb + rv * DD + h * 64 + e2 * 2);   // broadcast LDG.64

            #pragma unroll
            for (int j2 = 0; j2 < 2; ++j2) {
                const int e = e2 * 2 + j2;
                const ulonglong2* mrow =
                    reinterpret_cast<const ulonglong2*>(mw_sh + e * 132);
                const ulonglong2 m0 = mrow[dg];        // 256B + bcast: 2 wf
                const ulonglong2 m1 = mrow[dg + 16];
                #pragma unroll
                for (int rv = 0; rv < 4; ++rv) {
                    unsigned long long pr;
                    PACK2(pr, __float_as_uint(j2 ? ya[rv].y : ya[rv].x));
                    FMA2(acc[rv][0][0], m0.x, pr);
                    FMA2(acc[rv][0][1], m0.y, pr);
                    FMA2(acc[rv][1][0], m1.x, pr);
                    FMA2(acc[rv][1][1], m1.y, pr);
                }
            }
        }
    }

    #pragma unroll
    for (int rv = 0; rv < 4; ++rv) {
        float* vrow = g_v + (size_t)(rbase + rv) * DD;
        #pragma unroll
        for (int j = 0; j < 2; ++j) {
            unsigned v0, v1, v2, v3;
            UNPACK2(v0, v1, acc[rv][j][0]);
            UNPACK2(v2, v3, acc[rv][j][1]);
            float4 o = make_float4(__uint_as_float(v0), __uint_as_float(v1),
                                   __uint_as_float(v2), __uint_as_float(v3));
            *reinterpret_cast<float4*>(vrow + 4 * dg + 64 * j) = o;
        }
    }
}

// ================= kernel 2: persistent fused review pipeline =================
// Software pipeline across grid-stride iterations: the NEXT review's 8 wemb
// row gathers are issued right after the current z-partial frees ev[].
// K-softmax runs in warp 0 only -> p_sh; r_s phase reads p via LDS broadcast.
__global__ void __launch_bounds__(256, 4) review_kernel(
    const int*   __restrict__ tok,    // [R,S]
    const float* __restrict__ wemb,   // [V,D]
    const float* __restrict__ Ww,     // [D,K]
    const float* __restrict__ Wb,     // [K]
    const float* __restrict__ Tw,     // [K,D]
    const float* __restrict__ Tb)     // [D]
{
    __shared__ float wwS[KK * 129];   // [k][d], stride 129 -> bank (k+d)%32
    __shared__ float twS[KK * DD];    // [k][d]
    __shared__ float wb_sh[KK];
    __shared__ float v_sh[DD];
    __shared__ float ax_sh[SS];
    __shared__ float red[8 * DD];     // per-warp z partials
    __shared__ float z_sh[DD];
    __shared__ float lpart[8 * KK];
    __shared__ float p_sh[KK];

    const int t    = threadIdx.x;
    const int lane = t & 31;
    const int w    = t >> 5;

    // ---- one-time per-block staging ----
    for (int i = t; i < DD * KK; i += 256) {
        int d = i >> 5, k = i & 31;
        wwS[k * 129 + d] = Ww[i];
        twS[i] = Tw[i];
    }
    if (t < KK) wb_sh[t] = Wb[t];
    const float tb_reg = (t < DD) ? Tb[t] : 0.f;
    const int   part   = t >> 5;
    const float* wwrow = wwS + lane * 129 + part * 16;   // lane = logit k

    // ---- prologue: first review's tokens (per-warp regs), v, and gathers ----
    const int rfirst = blockIdx.x;
    int tokreg = 0;
    if (lane < 8) tokreg = __ldg(tok + rfirst * SS + w * 8 + lane);
    float v_pf = (t < DD) ? g_v[(size_t)rfirst * DD + t] : 0.f;

    float4 ev[8];
    #pragma unroll
    for (int i = 0; i < 8; ++i) {
        int id = __shfl_sync(0xffffffffu, tokreg, i);
        ev[i] = reinterpret_cast<const float4*>(wemb + (size_t)id * DD)[lane];
    }
    if (t < DD) v_sh[t] = v_pf;
    __syncthreads();

    for (int r = rfirst; r < RR; r += GRID_REVIEW) {
        const int rn = r + GRID_REVIEW;
        const int rc = (rn < RR) ? rn : r;

        const float4 v4 = reinterpret_cast<float4*>(v_sh)[lane];

        // ---- per-lane partial dots for this warp's 8 s-values ----
        float p[8];
        #pragma unroll
        for (int i = 0; i < 8; ++i)
            p[i] = ev[i].x * v4.x + ev[i].y * v4.y +
                   ev[i].z * v4.z + ev[i].w * v4.w;

        // ---- prefetch next review's tokens + v (regs; consumed in tail) ----
        int tokreg_n = 0;
        if (lane < 8) tokreg_n = __ldg(tok + rc * SS + w * 8 + lane);
        float v_pf_n = (t < DD) ? g_v[(size_t)rc * DD + t] : 0.f;

        // ---- folding multi-reduce: 8 dots -> 9 shfls ----
        float q[4];
        #pragma unroll
        for (int i = 0; i < 4; ++i) {
            float send = (lane & 16) ? p[i] : p[i + 4];
            float keep = (lane & 16) ? p[i + 4] : p[i];
            q[i] = keep + __shfl_xor_sync(0xffffffffu, send, 16);
        }
        float u[2];
        #pragma unroll
        for (int i = 0; i < 2; ++i) {
            float send = (lane & 8) ? q[i] : q[i + 2];
            float keep = (lane & 8) ? q[i + 2] : q[i];
            u[i] = keep + __shfl_xor_sync(0xffffffffu, send, 8);
        }
        float dx;
        {
            float send = (lane & 4) ? u[0] : u[1];
            float keep = (lane & 4) ? u[1] : u[0];
            dx = keep + __shfl_xor_sync(0xffffffffu, send, 4);
        }
        dx += __shfl_xor_sync(0xffffffffu, dx, 2);
        dx += __shfl_xor_sync(0xffffffffu, dx, 1);
        if ((lane & 3) == 0) ax_sh[w * 8 + ((lane >> 2) & 7)] = dx;
        __syncthreads();                                   // B1

        // ---- softmax over S=64 (redundant in every warp) + z partial ----
        float4 z = make_float4(0.f, 0.f, 0.f, 0.f);
        {
            float a = ax_sh[lane];
            float b = ax_sh[lane + 32];
            float m = fmaxf(a, b);
            #pragma unroll
            for (int o = 16; o; o >>= 1) m = fmaxf(m, __shfl_xor_sync(0xffffffffu, m, o));
            float ea = __expf(a - m), eb = __expf(b - m);
            float s = ea + eb;
            #pragma unroll
            for (int o = 16; o; o >>= 1) s += __shfl_xor_sync(0xffffffffu, s, o);
            float inv = __fdividef(1.f, s);
            float sel  = (w & 4) ? eb : ea;
            int   base = (w & 3) * 8;
            #pragma unroll
            for (int i = 0; i < 8; ++i) {
                float av = __shfl_sync(0xffffffffu, sel, base + i) * inv;
                z.x = fmaf(av, ev[i].x, z.x);
                z.y = fmaf(av, ev[i].y, z.y);
                z.z = fmaf(av, ev[i].z, z.z);
                z.w = fmaf(av, ev[i].w, z.w);
            }
        }

        // ---- ev[] now dead: ISSUE NEXT REVIEW'S GATHERS (latency hides
        //      under the whole aspect tail below) ----
        #pragma unroll
        for (int i = 0; i < 8; ++i) {
            int id = __shfl_sync(0xffffffffu, tokreg_n, i);
            ev[i] = reinterpret_cast<const float4*>(wemb + (size_t)id * DD)[lane];
        }

        reinterpret_cast<float4*>(red)[w * 32 + lane] = z;
        __syncthreads();                                   // B2

        // ---- z[d]: cross-warp sum of 8 partials ----
        if (t < DD) {
            float s = 0.f;
            #pragma unroll
            for (int w2 = 0; w2 < 8; ++w2)
                s += red[w2 * DD + t];
            z_sh[t] = s;
        }
        __syncthreads();                                   // B3

        // ---- aspect logits: thread (part, lane=k) -> 16-d partial ----
        {
            float a = 0.f;
            const float* zp = z_sh + part * 16;
            #pragma unroll
            for (int j = 0; j < 16; ++j)
                a = fmaf(zp[j], wwrow[j], a);
            lpart[part * KK + lane] = a;
        }
        __syncthreads();                                   // B4

        // ---- K-softmax: warp 0 only -> p_sh ----
        if (w == 0) {
            float a = wb_sh[lane];
            #pragma unroll
            for (int pp = 0; pp < 8; ++pp) a += lpart[pp * KK + lane];
            float m = a;
            #pragma unroll
            for (int o = 16; o; o >>= 1) m = fmaxf(m, __shfl_xor_sync(0xffffffffu, m, o));
            float e = __expf(a - m);
            float s = e;
            #pragma unroll
            for (int o = 16; o; o >>= 1) s += __shfl_xor_sync(0xffffffffu, s, o);
            p_sh[lane] = e * __fdividef(1.f, s);
        }
        __syncthreads();                                   // B5

        // ---- r_s[d] = Tb[d] + sum_k p[k] * Tw[k][d] (p via LDS broadcast) ----
        if (t < DD) {
            float a = tb_reg;
            #pragma unroll
            for (int k = 0; k < KK; ++k)
                a = fmaf(p_sh[k], twS[k * DD + t], a);
            g_rs[(size_t)r * DD + t] = a;
        }

        // ---- stage next v into SMEM; rotate token regs ----
        if (t < DD) v_sh[t] = v_pf_n;
        tokreg = tokreg_n;
        __syncthreads();   // B6: protects ax_sh/red/lpart/p_sh/v_sh for next iter
    }
}

// ================= kernel 3: fused segment-mean + prediction =================
__global__ void __launch_bounds__(256) final_kernel(
    const int*   __restrict__ user, const int* __restrict__ item,
    const int*   __restrict__ uidx, const int* __restrict__ iidx,
    const float* __restrict__ uemb, const float* __restrict__ iemb,
    const float* __restrict__ avg,  float* __restrict__ out)
{
    __shared__ float sh[256];
    __shared__ float red[4];

    const int b    = blockIdx.x;
    const int t    = threadIdx.x;
    const int side = t >> 7;          // 0 = user, 1 = item
    const int d    = t & 127;

    float uf = 0.f, itf = 0.f;
    if (t < DD) {
        uf  = uemb[(size_t)user[b] * DD + t];
        itf = iemb[(size_t)item[b] * DD + t];
    }

    const int* idxp = side ? iidx : uidx;
    const int  base = b * PER;

    int ids[PER];
    #pragma unroll
    for (int j = 0; j < PER; ++j)
        ids[j] = __ldg(idxp + base + j);      // PER independent LDG

    float sum = 0.f;
    #pragma unroll
    for (int j = 0; j < PER; ++j)
        sum += g_rs[(size_t)ids[j] * DD + d]; // PER independent LDG

    sh[t] = sum * (1.0f / (float)PER);
    __syncthreads();

    if (t < DD) {
        float p = sh[t] * sh[t + 128] + uf * itf;
        #pragma unroll
        for (int o = 16; o; o >>= 1) p += __shfl_xor_sync(0xffffffffu, p, o);
        if ((t & 31) == 0) red[t >> 5] = p;
    }
    __syncthreads();
    if (t == 0) out[b] = red[0] + red[1] + red[2] + red[3] + avg[0];
}

// ---------------- launch ----------------
extern "C" void kernel_launch(void* const* d_in, const int* in_sizes, int n_in,
                              void* d_out, int out_size)
{
    const int*   user = (const int*)  d_in[0];
    const int*   item = (const int*)  d_in[1];
    const int*   hrev = (const int*)  d_in[2];
    const float* ypos = (const float*)d_in[3];
    const int*   uidx = (const int*)  d_in[4];
    const int*   iidx = (const int*)  d_in[6];
    const float* wemb = (const float*)d_in[8];
    const float* Mw   = (const float*)d_in[9];
    // d_in[10] = M_b: constant shift over s -> cancels in softmax, unused
    const float* Ww   = (const float*)d_in[11];
    const float* Wb   = (const float*)d_in[12];
    const float* Tw   = (const float*)d_in[13];
    const float* Tb   = (const float*)d_in[14];
    const float* uemb = (const float*)d_in[15];
    const float* iemb = (const float*)d_in[16];
    const float* avg  = (const float*)d_in[17];
    float* out = (float*)d_out;

    vprep_kernel <<<RR / 32, 128>>>(Mw, ypos);   // 625 blocks x 32 reviews, 1 wave
    review_kernel<<<GRID_REVIEW, 256>>>(hrev, wemb, Ww, Wb, Tw, Tb);
    final_kernel <<<BB, 256>>>(user, item, uidx, iidx, uemb, iemb, avg, out);
}